// round 15
// baseline (speedup 1.0000x reference)
#include <cuda_runtime.h>
#include <cuda_bf16.h>
#include <cstdint>
#include <math.h>

#define N_TOK 8192
#define DIM   2048
#define FF    5632
#define NE    8

// ===================== helpers =============================================
__device__ __forceinline__ uint32_t smem_to_u32(const void* p) {
    uint32_t a;
    asm("{ .reg .u64 t; cvta.to.shared.u64 t, %1; cvt.u32.u64 %0, t; }"
        : "=r"(a) : "l"(p));
    return a;
}

#define LDSM_X4(r0, r1, r2, r3, addr) \
    asm volatile("ldmatrix.sync.aligned.m8n8.x4.shared.b16 {%0,%1,%2,%3}, [%4];" \
                 : "=r"(r0), "=r"(r1), "=r"(r2), "=r"(r3) : "r"(addr))

// NOTE: intentionally NOT volatile — pure register op, lets ptxas schedule.
#define MMA16816(c, a, b0, b1) \
    asm("mma.sync.aligned.m16n8k16.row.col.f32.bf16.bf16.f32 " \
        "{%0,%1,%2,%3},{%4,%5,%6,%7},{%8,%9},{%0,%1,%2,%3};" \
        : "+f"((c)[0]), "+f"((c)[1]), "+f"((c)[2]), "+f"((c)[3]) \
        : "r"((a)[0]), "r"((a)[1]), "r"((a)[2]), "r"((a)[3]), \
          "r"(b0), "r"(b1))

#define CP_ASYNC16(saddr, gptr) \
    asm volatile("cp.async.cg.shared.global [%0], [%1], 16;" \
                 :: "r"(saddr), "l"(gptr) : "memory")
#define CP_COMMIT() asm volatile("cp.async.commit_group;" ::: "memory")
#define CP_WAIT1()  asm volatile("cp.async.wait_group 1;" ::: "memory")

// fp32 -> (hi,lo) bf16 split, 2 values packed per uint32
__device__ __forceinline__ void split2(float a, float b, uint32_t& hi, uint32_t& lo) {
    __nv_bfloat16 ha = __float2bfloat16_rn(a);
    __nv_bfloat16 hb = __float2bfloat16_rn(b);
    float ra = a - __bfloat162float(ha);
    float rb = b - __bfloat162float(hb);
    __nv_bfloat162 h; h.x = ha; h.y = hb;
    __nv_bfloat162 l; l.x = __float2bfloat16_rn(ra); l.y = __float2bfloat16_rn(rb);
    hi = *reinterpret_cast<uint32_t*>(&h);
    lo = *reinterpret_cast<uint32_t*>(&l);
}

// byte offset within a [rows][32 bf16] tile, 64B rows, xor swizzle for ldmatrix
__device__ __forceinline__ uint32_t tile_off(int row, int chunk) {
    return (uint32_t)(row * 64 + ((chunk ^ ((row >> 1) & 3)) << 4));
}

// ===================== scratch =============================================
__device__ int   g_cnt[NE];
__device__ float g_psum[NE];
__device__ int   g_off[NE];
__device__ int   g_cursor[NE];
__device__ int   g_top_id[N_TOK * 2];
__device__ float g_top_w[N_TOK * 2];
__device__ int   g_row_tok[N_TOK * 2];
__device__ float g_row_w[N_TOK * 2];
__device__ __align__(16) __nv_bfloat16 g_Hhi[(size_t)N_TOK * 2 * FF];
__device__ __align__(16) __nv_bfloat16 g_Hlo[(size_t)N_TOK * 2 * FF];
// pre-split operands
__device__ __align__(16) __nv_bfloat16 g_xhi[(size_t)N_TOK * DIM];
__device__ __align__(16) __nv_bfloat16 g_xlo[(size_t)N_TOK * DIM];
__device__ __align__(16) __nv_bfloat16 g_gwhi[(size_t)NE * FF * DIM];
__device__ __align__(16) __nv_bfloat16 g_gwlo[(size_t)NE * FF * DIM];
__device__ __align__(16) __nv_bfloat16 g_uwhi[(size_t)NE * FF * DIM];
__device__ __align__(16) __nv_bfloat16 g_uwlo[(size_t)NE * FF * DIM];
__device__ __align__(16) __nv_bfloat16 g_dwhi[(size_t)NE * DIM * FF];
__device__ __align__(16) __nv_bfloat16 g_dwlo[(size_t)NE * DIM * FF];

// ===================== split (+ counter zero) ===============================
__global__ __launch_bounds__(256)
void split_all_kernel(const float* __restrict__ x, const float* __restrict__ gw,
                      const float* __restrict__ uw, const float* __restrict__ dw) {
    if (blockIdx.x == 0 && threadIdx.x < NE) {
        g_cnt[threadIdx.x] = 0;
        g_psum[threadIdx.x] = 0.f;
    }
    const size_t nx = (size_t)N_TOK * DIM;
    const size_t nw = (size_t)NE * FF * DIM;
    size_t i = ((size_t)blockIdx.x * blockDim.x + threadIdx.x) * 8;
    const float* src;
    __nv_bfloat16 *hi, *lo;
    size_t base;
    if (i < nx)               { src = x;  hi = g_xhi;  lo = g_xlo;  base = 0; }
    else if (i < nx + nw)     { src = gw; hi = g_gwhi; lo = g_gwlo; base = nx; }
    else if (i < nx + 2 * nw) { src = uw; hi = g_uwhi; lo = g_uwlo; base = nx + nw; }
    else if (i < nx + 3 * nw) { src = dw; hi = g_dwhi; lo = g_dwlo; base = nx + 2 * nw; }
    else return;
    size_t j = i - base;
    float4 a = *(const float4*)(src + j);
    float4 b = *(const float4*)(src + j + 4);
    uint32_t h0, l0, h1, l1, h2, l2, h3, l3;
    split2(a.x, a.y, h0, l0);
    split2(a.z, a.w, h1, l1);
    split2(b.x, b.y, h2, l2);
    split2(b.z, b.w, h3, l3);
    *(uint4*)(hi + j) = make_uint4(h0, h1, h2, h3);
    *(uint4*)(lo + j) = make_uint4(l0, l1, l2, l3);
}

// ===================== router ===============================================
__global__ void router_kernel(const float* __restrict__ x,
                              const float* __restrict__ rw) {
    int warp = threadIdx.x >> 5;
    int lane = threadIdx.x & 31;
    int t = blockIdx.x * 8 + warp;
    if (t >= N_TOK) return;
    const float* xr = x + (size_t)t * DIM;
    float acc[NE];
#pragma unroll
    for (int e = 0; e < NE; e++) acc[e] = 0.f;
    for (int d = lane; d < DIM; d += 32) {
        float xv = xr[d];
#pragma unroll
        for (int e = 0; e < NE; e++) acc[e] += xv * rw[e * DIM + d];
    }
#pragma unroll
    for (int off = 16; off > 0; off >>= 1) {
#pragma unroll
        for (int e = 0; e < NE; e++)
            acc[e] += __shfl_xor_sync(0xffffffffu, acc[e], off);
    }
    float mx = acc[0];
#pragma unroll
    for (int e = 1; e < NE; e++) mx = fmaxf(mx, acc[e]);
    float p[NE], s = 0.f;
#pragma unroll
    for (int e = 0; e < NE; e++) { p[e] = expf(acc[e] - mx); s += p[e]; }
    float inv = 1.f / s;
#pragma unroll
    for (int e = 0; e < NE; e++) p[e] *= inv;
    float m1 = -1.f, m2 = -1.f; int i1 = 0, i2 = 0;
#pragma unroll
    for (int e = 0; e < NE; e++) {
        if (p[e] > m1) { m2 = m1; i2 = i1; m1 = p[e]; i1 = e; }
        else if (p[e] > m2) { m2 = p[e]; i2 = e; }
    }
    if (lane == 0) {
        atomicAdd(&g_cnt[i1], 1);
        atomicAdd(&g_cnt[i2], 1);
#pragma unroll
        for (int e = 0; e < NE; e++) atomicAdd(&g_psum[e], p[e]);
        float sw = 1.f / (m1 + m2);
        g_top_id[2 * t + 0] = i1;  g_top_w[2 * t + 0] = m1 * sw;
        g_top_id[2 * t + 1] = i2;  g_top_w[2 * t + 1] = m2 * sw;
    }
}

// ===================== finalize + scatter (single block) ====================
__global__ __launch_bounds__(256)
void finscat_kernel(float* __restrict__ out, long long out_size) {
    int tid = threadIdx.x;
    if (tid == 0) {
        int o = 0;
        for (int e = 0; e < NE; e++) { g_off[e] = o; g_cursor[e] = o; o += g_cnt[e]; }
        float aux = 0.f;
        for (int e = 0; e < NE; e++) aux += g_psum[e] * (float)g_cnt[e];
        aux *= (float)NE / ((float)N_TOK * (float)N_TOK);
        if (out_size > (long long)N_TOK * DIM)
            out[(size_t)N_TOK * DIM] = aux;
    }
    __syncthreads();
    for (int t = tid; t < N_TOK; t += 256) {
#pragma unroll
        for (int s = 0; s < 2; s++) {
            int e = g_top_id[2 * t + s];
            int pos = atomicAdd(&g_cursor[e], 1);
            g_row_tok[pos] = t;
            g_row_w[pos] = g_top_w[2 * t + s];
        }
    }
}

// ===================== GEMM1: H = silu(X Gw^T) * (X Uw^T) ===================
// 3-stage cp.async pipeline, pre-split bf16 operands. CTA 128x64, BK=32,
// 256 thr, 8 warps (4x2), 2 CTAs/SM. ONE barrier per stage (trailing barrier
// removed: top-of-loop barrier of iter s+1 already orders compute(s) before
// fill(s+1), which reuses compute(s)'s buffer).
#define S1_AH 0
#define S1_AL 8192
#define S1_GH 16384
#define S1_GL 20480
#define S1_UH 24576
#define S1_UL 28672
#define STAGE1 32768
#define G1_SMEM (3 * STAGE1)

__global__ __launch_bounds__(256, 2)
void gemm1_mma() {
    int e   = blockIdx.z;
    int cnt = g_cnt[e];
    int m0  = blockIdx.y * 128;
    if (m0 >= cnt) return;
    int n0  = blockIdx.x * 64;
    int off = g_off[e];

    extern __shared__ char sm[];
    __shared__ int s_tok[128];
    int tid = threadIdx.x;
    if (tid < 128) {
        int rr = m0 + tid;
        s_tok[tid] = (rr < cnt) ? g_row_tok[off + rr] : g_row_tok[off];
    }
    __syncthreads();
    uint32_t sbu = smem_to_u32(sm);

    int rowA0 = tid >> 2;
    int rowA1 = 64 + (tid >> 2);
    int seg   = tid & 3;
    uint32_t offA0 = tile_off(rowA0, seg);
    uint32_t offA1 = tile_off(rowA1, seg);
    uint32_t offB  = offA0;
    const __nv_bfloat16* gA0h = g_xhi + (size_t)s_tok[rowA0] * DIM + seg * 8;
    const __nv_bfloat16* gA0l = g_xlo + (size_t)s_tok[rowA0] * DIM + seg * 8;
    const __nv_bfloat16* gA1h = g_xhi + (size_t)s_tok[rowA1] * DIM + seg * 8;
    const __nv_bfloat16* gA1l = g_xlo + (size_t)s_tok[rowA1] * DIM + seg * 8;
    size_t brow = (size_t)e * FF + n0 + rowA0;
    const __nv_bfloat16* gGh = g_gwhi + brow * DIM + seg * 8;
    const __nv_bfloat16* gGl = g_gwlo + brow * DIM + seg * 8;
    const __nv_bfloat16* gUh = g_uwhi + brow * DIM + seg * 8;
    const __nv_bfloat16* gUl = g_uwlo + brow * DIM + seg * 8;

    int lane = tid & 31, warp = tid >> 5;
    int wm = warp & 3, wn = warp >> 2;
    int laneA_row = lane & 15;
    int laneA_c   = lane >> 4;
    int laneB_row = (lane & 7) | ((lane >> 1) & 8);
    int laneB_c   = (lane >> 3) & 1;

    float gacc[2][4][4], uacc[2][4][4];
#pragma unroll
    for (int i = 0; i < 2; i++)
#pragma unroll
        for (int j = 0; j < 4; j++)
#pragma unroll
            for (int k = 0; k < 4; k++) { gacc[i][j][k] = 0.f; uacc[i][j][k] = 0.f; }

    const int NS = DIM / 32;  // 64

#define G1_FILL(s_, buf_) do { \
    uint32_t sb_ = sbu + (uint32_t)(buf_) * STAGE1; \
    int k0_ = (s_) * 32; \
    CP_ASYNC16(sb_ + S1_AH + offA0, gA0h + k0_); \
    CP_ASYNC16(sb_ + S1_AH + offA1, gA1h + k0_); \
    CP_ASYNC16(sb_ + S1_AL + offA0, gA0l + k0_); \
    CP_ASYNC16(sb_ + S1_AL + offA1, gA1l + k0_); \
    CP_ASYNC16(sb_ + S1_GH + offB,  gGh + k0_); \
    CP_ASYNC16(sb_ + S1_GL + offB,  gGl + k0_); \
    CP_ASYNC16(sb_ + S1_UH + offB,  gUh + k0_); \
    CP_ASYNC16(sb_ + S1_UL + offB,  gUl + k0_); \
    CP_COMMIT(); \
} while (0)

    G1_FILL(0, 0); G1_FILL(1, 1);
    int cbuf = 0, fbuf = 2;

#pragma unroll 1
    for (int s = 0; s < NS; s++) {
        CP_WAIT1();
        __syncthreads();
        if (s + 2 < NS) G1_FILL(s + 2, fbuf);
        fbuf = (fbuf == 2) ? 0 : fbuf + 1;
        uint32_t sb = sbu + (uint32_t)cbuf * STAGE1;
        cbuf = (cbuf == 2) ? 0 : cbuf + 1;
#pragma unroll
        for (int kk = 0; kk < 2; kk++) {
            int c0 = kk * 2;
            uint32_t ah[2][4], al[2][4];
#pragma unroll
            for (int mt = 0; mt < 2; mt++) {
                int row = wm * 32 + mt * 16 + laneA_row;
                int ch  = c0 + laneA_c;
                uint32_t ad = sb + S1_AH + tile_off(row, ch);
                LDSM_X4(ah[mt][0], ah[mt][1], ah[mt][2], ah[mt][3], ad);
                LDSM_X4(al[mt][0], al[mt][1], al[mt][2], al[mt][3], ad + (S1_AL - S1_AH));
            }
            {   // gate — term-major
                uint32_t bh[2][4], bl[2][4];
#pragma unroll
                for (int g2 = 0; g2 < 2; g2++) {
                    int row = wn * 32 + g2 * 16 + laneB_row;
                    int ch  = c0 + laneB_c;
                    uint32_t bd = sb + S1_GH + tile_off(row, ch);
                    LDSM_X4(bh[g2][0], bh[g2][1], bh[g2][2], bh[g2][3], bd);
                    LDSM_X4(bl[g2][0], bl[g2][1], bl[g2][2], bl[g2][3], bd + (S1_GL - S1_GH));
                }
#pragma unroll
                for (int mt = 0; mt < 2; mt++)
#pragma unroll
                    for (int nt = 0; nt < 4; nt++) {
                        int gi = nt >> 1, pi = (nt & 1) * 2;
                        MMA16816(gacc[mt][nt], ah[mt], bh[gi][pi], bh[gi][pi + 1]);
                    }
#pragma unroll
                for (int mt = 0; mt < 2; mt++)
#pragma unroll
                    for (int nt = 0; nt < 4; nt++) {
                        int gi = nt >> 1, pi = (nt & 1) * 2;
                        MMA16816(gacc[mt][nt], ah[mt], bl[gi][pi], bl[gi][pi + 1]);
                    }
#pragma unroll
                for (int mt = 0; mt < 2; mt++)
#pragma unroll
                    for (int nt = 0; nt < 4; nt++) {
                        int gi = nt >> 1, pi = (nt & 1) * 2;
                        MMA16816(gacc[mt][nt], al[mt], bh[gi][pi], bh[gi][pi + 1]);
                    }
            }
            {   // up — term-major
                uint32_t bh[2][4], bl[2][4];
#pragma unroll
                for (int g2 = 0; g2 < 2; g2++) {
                    int row = wn * 32 + g2 * 16 + laneB_row;
                    int ch  = c0 + laneB_c;
                    uint32_t bd = sb + S1_UH + tile_off(row, ch);
                    LDSM_X4(bh[g2][0], bh[g2][1], bh[g2][2], bh[g2][3], bd);
                    LDSM_X4(bl[g2][0], bl[g2][1], bl[g2][2], bl[g2][3], bd + (S1_UL - S1_UH));
                }
#pragma unroll
                for (int mt = 0; mt < 2; mt++)
#pragma unroll
                    for (int nt = 0; nt < 4; nt++) {
                        int gi = nt >> 1, pi = (nt & 1) * 2;
                        MMA16816(uacc[mt][nt], ah[mt], bh[gi][pi], bh[gi][pi + 1]);
                    }
#pragma unroll
                for (int mt = 0; mt < 2; mt++)
#pragma unroll
                    for (int nt = 0; nt < 4; nt++) {
                        int gi = nt >> 1, pi = (nt & 1) * 2;
                        MMA16816(uacc[mt][nt], ah[mt], bl[gi][pi], bl[gi][pi + 1]);
                    }
#pragma unroll
                for (int mt = 0; mt < 2; mt++)
#pragma unroll
                    for (int nt = 0; nt < 4; nt++) {
                        int gi = nt >> 1, pi = (nt & 1) * 2;
                        MMA16816(uacc[mt][nt], al[mt], bh[gi][pi], bh[gi][pi + 1]);
                    }
            }
        }
    }

    // epilogue: h = silu(g)*u -> split bf16 hi/lo -> g_H
#pragma unroll
    for (int mt = 0; mt < 2; mt++) {
#pragma unroll
        for (int half = 0; half < 2; half++) {
            int rr = m0 + wm * 32 + mt * 16 + (lane >> 2) + half * 8;
            if (rr < cnt) {
                size_t rb = (size_t)(off + rr) * FF + n0 + wn * 32 + (lane & 3) * 2;
#pragma unroll
                for (int nt = 0; nt < 4; nt++) {
                    float g0 = gacc[mt][nt][half * 2 + 0];
                    float g1 = gacc[mt][nt][half * 2 + 1];
                    float u0 = uacc[mt][nt][half * 2 + 0];
                    float u1 = uacc[mt][nt][half * 2 + 1];
                    float h0 = g0 / (1.f + __expf(-g0)) * u0;
                    float h1 = g1 / (1.f + __expf(-g1)) * u1;
                    uint32_t hh, hl;
                    split2(h0, h1, hh, hl);
                    *(uint32_t*)(g_Hhi + rb + nt * 8) = hh;
                    *(uint32_t*)(g_Hlo + rb + nt * 8) = hl;
                }
            }
        }
    }
}

// ===================== GEMM2: out += w * (H Dw^T) ===========================
#define S2_AH 0
#define S2_AL 8192
#define S2_BH 16384
#define S2_BL 20480
#define STAGE2 24576
#define G2_SMEM (3 * STAGE2)

__global__ __launch_bounds__(256, 2)
void gemm2_mma(float* __restrict__ out) {
    int e   = blockIdx.z;
    int cnt = g_cnt[e];
    int m0  = blockIdx.y * 128;
    if (m0 >= cnt) return;
    int n0  = blockIdx.x * 64;
    int off = g_off[e];

    extern __shared__ char sm[];
    __shared__ int   s_tok[128];
    __shared__ float s_w[128];
    int tid = threadIdx.x;
    if (tid < 128) {
        int rr = m0 + tid;
        bool v = rr < cnt;
        s_tok[tid] = v ? g_row_tok[off + rr] : 0;
        s_w[tid]   = v ? g_row_w[off + rr] : 0.f;
    }
    __syncthreads();
    uint32_t sbu = smem_to_u32(sm);

    int rowA0 = tid >> 2;
    int rowA1 = 64 + (tid >> 2);
    int seg   = tid & 3;
    uint32_t offA0 = tile_off(rowA0, seg);
    uint32_t offA1 = tile_off(rowA1, seg);
    uint32_t offB  = offA0;
    int hr0 = (m0 + rowA0 < cnt) ? (off + m0 + rowA0) : off;
    int hr1 = (m0 + rowA1 < cnt) ? (off + m0 + rowA1) : off;
    const __nv_bfloat16* gA0h = g_Hhi + (size_t)hr0 * FF + seg * 8;
    const __nv_bfloat16* gA0l = g_Hlo + (size_t)hr0 * FF + seg * 8;
    const __nv_bfloat16* gA1h = g_Hhi + (size_t)hr1 * FF + seg * 8;
    const __nv_bfloat16* gA1l = g_Hlo + (size_t)hr1 * FF + seg * 8;
    size_t brow = (size_t)e * DIM + n0 + rowA0;
    const __nv_bfloat16* gBh = g_dwhi + brow * FF + seg * 8;
    const __nv_bfloat16* gBl = g_dwlo + brow * FF + seg * 8;

    int lane = tid & 31, warp = tid >> 5;
    int wm = warp & 3, wn = warp >> 2;
    int laneA_row = lane & 15;
    int laneA_c   = lane >> 4;
    int laneB_row = (lane & 7) | ((lane >> 1) & 8);
    int laneB_c   = (lane >> 3) & 1;

    float acc[2][4][4];
#pragma unroll
    for (int i = 0; i < 2; i++)
#pragma unroll
        for (int j = 0; j < 4; j++)
#pragma unroll
            for (int k = 0; k < 4; k++) acc[i][j][k] = 0.f;

    const int NS = FF / 32;  // 176

#define G2_FILL(s_, buf_) do { \
    uint32_t sb_ = sbu + (uint32_t)(buf_) * STAGE2; \
    int k0_ = (s_) * 32; \
    CP_ASYNC16(sb_ + S2_AH + offA0, gA0h + k0_); \
    CP_ASYNC16(sb_ + S2_AH + offA1, gA1h + k0_); \
    CP_ASYNC16(sb_ + S2_AL + offA0, gA0l + k0_); \
    CP_ASYNC16(sb_ + S2_AL + offA1, gA1l + k0_); \
    CP_ASYNC16(sb_ + S2_BH + offB,  gBh + k0_); \
    CP_ASYNC16(sb_ + S2_BL + offB,  gBl + k0_); \
    CP_COMMIT(); \
} while (0)

    G2_FILL(0, 0); G2_FILL(1, 1);
    int cbuf = 0, fbuf = 2;

#pragma unroll 1
    for (int s = 0; s < NS; s++) {
        CP_WAIT1();
        __syncthreads();
        if (s + 2 < NS) G2_FILL(s + 2, fbuf);
        fbuf = (fbuf == 2) ? 0 : fbuf + 1;
        uint32_t sb = sbu + (uint32_t)cbuf * STAGE2;
        cbuf = (cbuf == 2) ? 0 : cbuf + 1;
#pragma unroll
        for (int kk = 0; kk < 2; kk++) {
            int c0 = kk * 2;
            uint32_t ah[2][4], al[2][4];
#pragma unroll
            for (int mt = 0; mt < 2; mt++) {
                int row = wm * 32 + mt * 16 + laneA_row;
                int ch  = c0 + laneA_c;
                uint32_t ad = sb + S2_AH + tile_off(row, ch);
                LDSM_X4(ah[mt][0], ah[mt][1], ah[mt][2], ah[mt][3], ad);
                LDSM_X4(al[mt][0], al[mt][1], al[mt][2], al[mt][3], ad + (S2_AL - S2_AH));
            }
            uint32_t bh[2][4], bl[2][4];
#pragma unroll
            for (int g2 = 0; g2 < 2; g2++) {
                int row = wn * 32 + g2 * 16 + laneB_row;
                int ch  = c0 + laneB_c;
                uint32_t bd = sb + S2_BH + tile_off(row, ch);
                LDSM_X4(bh[g2][0], bh[g2][1], bh[g2][2], bh[g2][3], bd);
                LDSM_X4(bl[g2][0], bl[g2][1], bl[g2][2], bl[g2][3], bd + (S2_BL - S2_BH));
            }
            // term-major
#pragma unroll
            for (int mt = 0; mt < 2; mt++)
#pragma unroll
                for (int nt = 0; nt < 4; nt++) {
                    int gi = nt >> 1, pi = (nt & 1) * 2;
                    MMA16816(acc[mt][nt], ah[mt], bh[gi][pi], bh[gi][pi + 1]);
                }
#pragma unroll
            for (int mt = 0; mt < 2; mt++)
#pragma unroll
                for (int nt = 0; nt < 4; nt++) {
                    int gi = nt >> 1, pi = (nt & 1) * 2;
                    MMA16816(acc[mt][nt], ah[mt], bl[gi][pi], bl[gi][pi + 1]);
                }
#pragma unroll
            for (int mt = 0; mt < 2; mt++)
#pragma unroll
                for (int nt = 0; nt < 4; nt++) {
                    int gi = nt >> 1, pi = (nt & 1) * 2;
                    MMA16816(acc[mt][nt], al[mt], bh[gi][pi], bh[gi][pi + 1]);
                }
        }
    }

    // epilogue: weighted scatter-add (exactly 2 adds/element)
#pragma unroll
    for (int mt = 0; mt < 2; mt++) {
#pragma unroll
        for (int half = 0; half < 2; half++) {
            int lrow = wm * 32 + mt * 16 + (lane >> 2) + half * 8;
            int rr = m0 + lrow;
            if (rr < cnt) {
                int tok = s_tok[lrow];
                float w = s_w[lrow];
                float* orow = out + (size_t)tok * DIM + n0 + wn * 32 + (lane & 3) * 2;
#pragma unroll
                for (int nt = 0; nt < 4; nt++) {
                    atomicAdd(orow + nt * 8 + 0, w * acc[mt][nt][half * 2 + 0]);
                    atomicAdd(orow + nt * 8 + 1, w * acc[mt][nt][half * 2 + 1]);
                }
            }
        }
    }
}

// ===================== launcher =============================================
extern "C" void kernel_launch(void* const* d_in, const int* in_sizes, int n_in,
                              void* d_out, int out_size) {
    const float* x  = (const float*)d_in[0];
    const float* rw = (const float*)d_in[1];
    const float* gw = (const float*)d_in[2];
    const float* uw = (const float*)d_in[3];
    const float* dw = (const float*)d_in[4];
    float* out = (float*)d_out;

    cudaFuncSetAttribute(gemm1_mma, cudaFuncAttributeMaxDynamicSharedMemorySize, G1_SMEM);
    cudaFuncSetAttribute(gemm2_mma, cudaFuncAttributeMaxDynamicSharedMemorySize, G2_SMEM);

    // launch order (harness adds 2 internal launches; ncu -s 5 -c 1 captures
    // overall launch #5 = our index 3 = gemm1_mma):
    // split_all(0) router(1) finscat(2) gemm1(3) memset(4) gemm2(5)
    {
        size_t total = (size_t)N_TOK * DIM + 3 * (size_t)NE * FF * DIM;
        split_all_kernel<<<(unsigned)(total / 2048), 256>>>(x, gw, uw, dw);
    }
    router_kernel<<<N_TOK / 8, 256>>>(x, rw);
    finscat_kernel<<<1, 256>>>(out, (long long)out_size);
    gemm1_mma<<<dim3(FF / 64, 2 * N_TOK / 128, NE), 256, G1_SMEM>>>();
    cudaMemsetAsync(out, 0, (size_t)N_TOK * DIM * sizeof(float));
    gemm2_mma<<<dim3(DIM / 64, 2 * N_TOK / 128, NE), 256, G2_SMEM>>>(out);
}

// round 16
// speedup vs baseline: 1.4594x; 1.4594x over previous
#include <cuda_runtime.h>
#include <cuda_fp16.h>
#include <cstdint>
#include <math.h>

#define N_TOK 8192
#define DIM   2048
#define FF    5632
#define NE    8

// ===================== helpers =============================================
__device__ __forceinline__ uint32_t smem_to_u32(const void* p) {
    uint32_t a;
    asm("{ .reg .u64 t; cvta.to.shared.u64 t, %1; cvt.u32.u64 %0, t; }"
        : "=r"(a) : "l"(p));
    return a;
}

#define LDSM_X4(r0, r1, r2, r3, addr) \
    asm volatile("ldmatrix.sync.aligned.m8n8.x4.shared.b16 {%0,%1,%2,%3}, [%4];" \
                 : "=r"(r0), "=r"(r1), "=r"(r2), "=r"(r3) : "r"(addr))

// fp16 MMA, fp32 accum. NOT volatile — lets ptxas schedule.
#define MMAF16(c, a, b0, b1) \
    asm("mma.sync.aligned.m16n8k16.row.col.f32.f16.f16.f32 " \
        "{%0,%1,%2,%3},{%4,%5,%6,%7},{%8,%9},{%0,%1,%2,%3};" \
        : "+f"((c)[0]), "+f"((c)[1]), "+f"((c)[2]), "+f"((c)[3]) \
        : "r"((a)[0]), "r"((a)[1]), "r"((a)[2]), "r"((a)[3]), \
          "r"(b0), "r"(b1))

#define CP_ASYNC16(saddr, gptr) \
    asm volatile("cp.async.cg.shared.global [%0], [%1], 16;" \
                 :: "r"(saddr), "l"(gptr) : "memory")
#define CP_COMMIT() asm volatile("cp.async.commit_group;" ::: "memory")
#define CP_WAIT2()  asm volatile("cp.async.wait_group 2;" ::: "memory")

// fp32 pair -> packed fp16 hi pair + packed fp16 lo pair
__device__ __forceinline__ void split2h(float a, float b, uint32_t& hi, uint32_t& lo) {
    __half ha = __float2half_rn(a);
    __half hb = __float2half_rn(b);
    float ra = a - __half2float(ha);
    float rb = b - __half2float(hb);
    __half2 h = __halves2half2(ha, hb);
    __half2 l = __halves2half2(__float2half_rn(ra), __float2half_rn(rb));
    hi = *reinterpret_cast<uint32_t*>(&h);
    lo = *reinterpret_cast<uint32_t*>(&l);
}
// fp32 pair -> packed fp16 pair (hi only)
__device__ __forceinline__ uint32_t pack2h(float a, float b) {
    __half2 h = __halves2half2(__float2half_rn(a), __float2half_rn(b));
    return *reinterpret_cast<uint32_t*>(&h);
}

// byte offset within a [rows][32 fp16] tile, 64B rows, xor swizzle for ldmatrix
__device__ __forceinline__ uint32_t tile_off(int row, int chunk) {
    return (uint32_t)(row * 64 + ((chunk ^ ((row >> 1) & 3)) << 4));
}

// ===================== scratch =============================================
__device__ int   g_cnt[NE];
__device__ float g_psum[NE];
__device__ int   g_off[NE];
__device__ int   g_cursor[NE];
__device__ int   g_top_id[N_TOK * 2];
__device__ float g_top_w[N_TOK * 2];
__device__ int   g_row_tok[N_TOK * 2];
__device__ float g_row_w[N_TOK * 2];
__device__ __align__(16) __half g_Hh[(size_t)N_TOK * 2 * FF];   // fp16 H (no lo)
// pre-split operands: x single fp16; weights fp16 hi/lo
__device__ __align__(16) __half g_xh [(size_t)N_TOK * DIM];
__device__ __align__(16) __half g_gwh[(size_t)NE * FF * DIM];
__device__ __align__(16) __half g_gwl[(size_t)NE * FF * DIM];
__device__ __align__(16) __half g_uwh[(size_t)NE * FF * DIM];
__device__ __align__(16) __half g_uwl[(size_t)NE * FF * DIM];
__device__ __align__(16) __half g_dwh[(size_t)NE * DIM * FF];
__device__ __align__(16) __half g_dwl[(size_t)NE * DIM * FF];

// ===================== split (+ counter zero) ===============================
__global__ __launch_bounds__(256)
void split_all_kernel(const float* __restrict__ x, const float* __restrict__ gw,
                      const float* __restrict__ uw, const float* __restrict__ dw) {
    if (blockIdx.x == 0 && threadIdx.x < NE) {
        g_cnt[threadIdx.x] = 0;
        g_psum[threadIdx.x] = 0.f;
    }
    const size_t nx = (size_t)N_TOK * DIM;
    const size_t nw = (size_t)NE * FF * DIM;
    size_t i = ((size_t)blockIdx.x * blockDim.x + threadIdx.x) * 8;
    if (i < nx) {   // x: hi only
        float4 a = *(const float4*)(x + i);
        float4 b = *(const float4*)(x + i + 4);
        *(uint4*)(g_xh + i) = make_uint4(pack2h(a.x, a.y), pack2h(a.z, a.w),
                                         pack2h(b.x, b.y), pack2h(b.z, b.w));
        return;
    }
    const float* src;
    __half *hi, *lo;
    size_t base;
    if (i < nx + nw)          { src = gw; hi = g_gwh; lo = g_gwl; base = nx; }
    else if (i < nx + 2 * nw) { src = uw; hi = g_uwh; lo = g_uwl; base = nx + nw; }
    else if (i < nx + 3 * nw) { src = dw; hi = g_dwh; lo = g_dwl; base = nx + 2 * nw; }
    else return;
    size_t j = i - base;
    float4 a = *(const float4*)(src + j);
    float4 b = *(const float4*)(src + j + 4);
    uint32_t h0, l0, h1, l1, h2, l2, h3, l3;
    split2h(a.x, a.y, h0, l0);
    split2h(a.z, a.w, h1, l1);
    split2h(b.x, b.y, h2, l2);
    split2h(b.z, b.w, h3, l3);
    *(uint4*)(hi + j) = make_uint4(h0, h1, h2, h3);
    *(uint4*)(lo + j) = make_uint4(l0, l1, l2, l3);
}

// ===================== router ===============================================
__global__ void router_kernel(const float* __restrict__ x,
                              const float* __restrict__ rw) {
    int warp = threadIdx.x >> 5;
    int lane = threadIdx.x & 31;
    int t = blockIdx.x * 8 + warp;
    if (t >= N_TOK) return;
    const float* xr = x + (size_t)t * DIM;
    float acc[NE];
#pragma unroll
    for (int e = 0; e < NE; e++) acc[e] = 0.f;
    for (int d = lane; d < DIM; d += 32) {
        float xv = xr[d];
#pragma unroll
        for (int e = 0; e < NE; e++) acc[e] += xv * rw[e * DIM + d];
    }
#pragma unroll
    for (int off = 16; off > 0; off >>= 1) {
#pragma unroll
        for (int e = 0; e < NE; e++)
            acc[e] += __shfl_xor_sync(0xffffffffu, acc[e], off);
    }
    float mx = acc[0];
#pragma unroll
    for (int e = 1; e < NE; e++) mx = fmaxf(mx, acc[e]);
    float p[NE], s = 0.f;
#pragma unroll
    for (int e = 0; e < NE; e++) { p[e] = expf(acc[e] - mx); s += p[e]; }
    float inv = 1.f / s;
#pragma unroll
    for (int e = 0; e < NE; e++) p[e] *= inv;
    float m1 = -1.f, m2 = -1.f; int i1 = 0, i2 = 0;
#pragma unroll
    for (int e = 0; e < NE; e++) {
        if (p[e] > m1) { m2 = m1; i2 = i1; m1 = p[e]; i1 = e; }
        else if (p[e] > m2) { m2 = p[e]; i2 = e; }
    }
    if (lane == 0) {
        atomicAdd(&g_cnt[i1], 1);
        atomicAdd(&g_cnt[i2], 1);
#pragma unroll
        for (int e = 0; e < NE; e++) atomicAdd(&g_psum[e], p[e]);
        float sw = 1.f / (m1 + m2);
        g_top_id[2 * t + 0] = i1;  g_top_w[2 * t + 0] = m1 * sw;
        g_top_id[2 * t + 1] = i2;  g_top_w[2 * t + 1] = m2 * sw;
    }
}

// ===================== finalize + scatter (single block) ====================
__global__ __launch_bounds__(256)
void finscat_kernel(float* __restrict__ out, long long out_size) {
    int tid = threadIdx.x;
    if (tid == 0) {
        int o = 0;
        for (int e = 0; e < NE; e++) { g_off[e] = o; g_cursor[e] = o; o += g_cnt[e]; }
        float aux = 0.f;
        for (int e = 0; e < NE; e++) aux += g_psum[e] * (float)g_cnt[e];
        aux *= (float)NE / ((float)N_TOK * (float)N_TOK);
        if (out_size > (long long)N_TOK * DIM)
            out[(size_t)N_TOK * DIM] = aux;
    }
    __syncthreads();
    for (int t = tid; t < N_TOK; t += 256) {
#pragma unroll
        for (int s = 0; s < 2; s++) {
            int e = g_top_id[2 * t + s];
            int pos = atomicAdd(&g_cursor[e], 1);
            g_row_tok[pos] = t;
            g_row_w[pos] = g_top_w[2 * t + s];
        }
    }
}

// ===================== GEMM1: H = silu(X Gw^T) * (X Uw^T) ===================
// fp16 2-term: C = Ah*(Bh+Bl). CTA 128x64, BK=32, 256 thr, 8 warps (4x2),
// 4-stage cp.async, 2 CTAs/SM. A = x fp16 single; gate/up fp16 hi+lo.
#define S1_A  0
#define S1_GH 8192
#define S1_GL 12288
#define S1_UH 16384
#define S1_UL 20480
#define STAGE1 24576
#define G1_SMEM (4 * STAGE1)

__global__ __launch_bounds__(256, 2)
void gemm1_mma() {
    int e   = blockIdx.z;
    int cnt = g_cnt[e];
    int m0  = blockIdx.y * 128;
    if (m0 >= cnt) return;
    int n0  = blockIdx.x * 64;
    int off = g_off[e];

    extern __shared__ char sm[];
    __shared__ int s_tok[128];
    int tid = threadIdx.x;
    if (tid < 128) {
        int rr = m0 + tid;
        s_tok[tid] = (rr < cnt) ? g_row_tok[off + rr] : g_row_tok[off];
    }
    __syncthreads();
    uint32_t sbu = smem_to_u32(sm);

    int rowA0 = tid >> 2;
    int rowA1 = 64 + (tid >> 2);
    int seg   = tid & 3;
    uint32_t offA0 = tile_off(rowA0, seg);
    uint32_t offA1 = tile_off(rowA1, seg);
    uint32_t offB  = offA0;
    const __half* gA0 = g_xh + (size_t)s_tok[rowA0] * DIM + seg * 8;
    const __half* gA1 = g_xh + (size_t)s_tok[rowA1] * DIM + seg * 8;
    size_t brow = (size_t)e * FF + n0 + rowA0;
    const __half* gGh = g_gwh + brow * DIM + seg * 8;
    const __half* gGl = g_gwl + brow * DIM + seg * 8;
    const __half* gUh = g_uwh + brow * DIM + seg * 8;
    const __half* gUl = g_uwl + brow * DIM + seg * 8;

    int lane = tid & 31, warp = tid >> 5;
    int wm = warp & 3, wn = warp >> 2;
    int laneA_row = lane & 15;
    int laneA_c   = lane >> 4;
    int laneB_row = (lane & 7) | ((lane >> 1) & 8);
    int laneB_c   = (lane >> 3) & 1;

    float gacc[2][4][4], uacc[2][4][4];
#pragma unroll
    for (int i = 0; i < 2; i++)
#pragma unroll
        for (int j = 0; j < 4; j++)
#pragma unroll
            for (int k = 0; k < 4; k++) { gacc[i][j][k] = 0.f; uacc[i][j][k] = 0.f; }

    const int NS = DIM / 32;  // 64

#define G1_FILL(s_) do { \
    uint32_t sb_ = sbu + (uint32_t)((s_) & 3) * STAGE1; \
    int k0_ = (s_) * 32; \
    CP_ASYNC16(sb_ + S1_A  + offA0, gA0 + k0_); \
    CP_ASYNC16(sb_ + S1_A  + offA1, gA1 + k0_); \
    CP_ASYNC16(sb_ + S1_GH + offB,  gGh + k0_); \
    CP_ASYNC16(sb_ + S1_GL + offB,  gGl + k0_); \
    CP_ASYNC16(sb_ + S1_UH + offB,  gUh + k0_); \
    CP_ASYNC16(sb_ + S1_UL + offB,  gUl + k0_); \
    CP_COMMIT(); \
} while (0)

    G1_FILL(0); G1_FILL(1); G1_FILL(2);

#pragma unroll 1
    for (int s = 0; s < NS; s++) {
        CP_WAIT2();
        __syncthreads();
        if (s + 3 < NS) G1_FILL(s + 3);
        uint32_t sb = sbu + (uint32_t)(s & 3) * STAGE1;
#pragma unroll
        for (int kk = 0; kk < 2; kk++) {
            int c0 = kk * 2;
            uint32_t ah[2][4];
#pragma unroll
            for (int mt = 0; mt < 2; mt++) {
                int row = wm * 32 + mt * 16 + laneA_row;
                int ch  = c0 + laneA_c;
                uint32_t ad = sb + S1_A + tile_off(row, ch);
                LDSM_X4(ah[mt][0], ah[mt][1], ah[mt][2], ah[mt][3], ad);
            }
            {   // gate: Ah*Bh sweep, then Ah*Bl sweep
                uint32_t bh[2][4], bl[2][4];
#pragma unroll
                for (int g2 = 0; g2 < 2; g2++) {
                    int row = wn * 32 + g2 * 16 + laneB_row;
                    int ch  = c0 + laneB_c;
                    uint32_t bd = sb + S1_GH + tile_off(row, ch);
                    LDSM_X4(bh[g2][0], bh[g2][1], bh[g2][2], bh[g2][3], bd);
                    LDSM_X4(bl[g2][0], bl[g2][1], bl[g2][2], bl[g2][3], bd + (S1_GL - S1_GH));
                }
#pragma unroll
                for (int mt = 0; mt < 2; mt++)
#pragma unroll
                    for (int nt = 0; nt < 4; nt++) {
                        int gi = nt >> 1, pi = (nt & 1) * 2;
                        MMAF16(gacc[mt][nt], ah[mt], bh[gi][pi], bh[gi][pi + 1]);
                    }
#pragma unroll
                for (int mt = 0; mt < 2; mt++)
#pragma unroll
                    for (int nt = 0; nt < 4; nt++) {
                        int gi = nt >> 1, pi = (nt & 1) * 2;
                        MMAF16(gacc[mt][nt], ah[mt], bl[gi][pi], bl[gi][pi + 1]);
                    }
            }
            {   // up
                uint32_t bh[2][4], bl[2][4];
#pragma unroll
                for (int g2 = 0; g2 < 2; g2++) {
                    int row = wn * 32 + g2 * 16 + laneB_row;
                    int ch  = c0 + laneB_c;
                    uint32_t bd = sb + S1_UH + tile_off(row, ch);
                    LDSM_X4(bh[g2][0], bh[g2][1], bh[g2][2], bh[g2][3], bd);
                    LDSM_X4(bl[g2][0], bl[g2][1], bl[g2][2], bl[g2][3], bd + (S1_UL - S1_UH));
                }
#pragma unroll
                for (int mt = 0; mt < 2; mt++)
#pragma unroll
                    for (int nt = 0; nt < 4; nt++) {
                        int gi = nt >> 1, pi = (nt & 1) * 2;
                        MMAF16(uacc[mt][nt], ah[mt], bh[gi][pi], bh[gi][pi + 1]);
                    }
#pragma unroll
                for (int mt = 0; mt < 2; mt++)
#pragma unroll
                    for (int nt = 0; nt < 4; nt++) {
                        int gi = nt >> 1, pi = (nt & 1) * 2;
                        MMAF16(uacc[mt][nt], ah[mt], bl[gi][pi], bl[gi][pi + 1]);
                    }
            }
        }
    }

    // epilogue: h = silu(g)*u -> fp16 -> g_Hh
#pragma unroll
    for (int mt = 0; mt < 2; mt++) {
#pragma unroll
        for (int half = 0; half < 2; half++) {
            int rr = m0 + wm * 32 + mt * 16 + (lane >> 2) + half * 8;
            if (rr < cnt) {
                size_t rb = (size_t)(off + rr) * FF + n0 + wn * 32 + (lane & 3) * 2;
#pragma unroll
                for (int nt = 0; nt < 4; nt++) {
                    float g0 = gacc[mt][nt][half * 2 + 0];
                    float g1 = gacc[mt][nt][half * 2 + 1];
                    float u0 = uacc[mt][nt][half * 2 + 0];
                    float u1 = uacc[mt][nt][half * 2 + 1];
                    float h0 = g0 / (1.f + __expf(-g0)) * u0;
                    float h1 = g1 / (1.f + __expf(-g1)) * u1;
                    *(uint32_t*)(g_Hh + rb + nt * 8) = pack2h(h0, h1);
                }
            }
        }
    }
}

// ===================== GEMM2: out += w * (H Dw^T) ===========================
// fp16 2-term: C = Hh*(Dh+Dl). A = H fp16 single; dw fp16 hi+lo.
#define S2_A  0
#define S2_BH 8192
#define S2_BL 12288
#define STAGE2 16384
#define G2_SMEM (4 * STAGE2)

__global__ __launch_bounds__(256, 2)
void gemm2_mma(float* __restrict__ out) {
    int e   = blockIdx.z;
    int cnt = g_cnt[e];
    int m0  = blockIdx.y * 128;
    if (m0 >= cnt) return;
    int n0  = blockIdx.x * 64;
    int off = g_off[e];

    extern __shared__ char sm[];
    __shared__ int   s_tok[128];
    __shared__ float s_w[128];
    int tid = threadIdx.x;
    if (tid < 128) {
        int rr = m0 + tid;
        bool v = rr < cnt;
        s_tok[tid] = v ? g_row_tok[off + rr] : 0;
        s_w[tid]   = v ? g_row_w[off + rr] : 0.f;
    }
    __syncthreads();
    uint32_t sbu = smem_to_u32(sm);

    int rowA0 = tid >> 2;
    int rowA1 = 64 + (tid >> 2);
    int seg   = tid & 3;
    uint32_t offA0 = tile_off(rowA0, seg);
    uint32_t offA1 = tile_off(rowA1, seg);
    uint32_t offB  = offA0;
    int hr0 = (m0 + rowA0 < cnt) ? (off + m0 + rowA0) : off;
    int hr1 = (m0 + rowA1 < cnt) ? (off + m0 + rowA1) : off;
    const __half* gA0 = g_Hh + (size_t)hr0 * FF + seg * 8;
    const __half* gA1 = g_Hh + (size_t)hr1 * FF + seg * 8;
    size_t brow = (size_t)e * DIM + n0 + rowA0;
    const __half* gBh = g_dwh + brow * FF + seg * 8;
    const __half* gBl = g_dwl + brow * FF + seg * 8;

    int lane = tid & 31, warp = tid >> 5;
    int wm = warp & 3, wn = warp >> 2;
    int laneA_row = lane & 15;
    int laneA_c   = lane >> 4;
    int laneB_row = (lane & 7) | ((lane >> 1) & 8);
    int laneB_c   = (lane >> 3) & 1;

    float acc[2][4][4];
#pragma unroll
    for (int i = 0; i < 2; i++)
#pragma unroll
        for (int j = 0; j < 4; j++)
#pragma unroll
            for (int k = 0; k < 4; k++) acc[i][j][k] = 0.f;

    const int NS = FF / 32;  // 176

#define G2_FILL(s_) do { \
    uint32_t sb_ = sbu + (uint32_t)((s_) & 3) * STAGE2; \
    int k0_ = (s_) * 32; \
    CP_ASYNC16(sb_ + S2_A  + offA0, gA0 + k0_); \
    CP_ASYNC16(sb_ + S2_A  + offA1, gA1 + k0_); \
    CP_ASYNC16(sb_ + S2_BH + offB,  gBh + k0_); \
    CP_ASYNC16(sb_ + S2_BL + offB,  gBl + k0_); \
    CP_COMMIT(); \
} while (0)

    G2_FILL(0); G2_FILL(1); G2_FILL(2);

#pragma unroll 1
    for (int s = 0; s < NS; s++) {
        CP_WAIT2();
        __syncthreads();
        if (s + 3 < NS) G2_FILL(s + 3);
        uint32_t sb = sbu + (uint32_t)(s & 3) * STAGE2;
#pragma unroll
        for (int kk = 0; kk < 2; kk++) {
            int c0 = kk * 2;
            uint32_t ah[2][4];
#pragma unroll
            for (int mt = 0; mt < 2; mt++) {
                int row = wm * 32 + mt * 16 + laneA_row;
                int ch  = c0 + laneA_c;
                uint32_t ad = sb + S2_A + tile_off(row, ch);
                LDSM_X4(ah[mt][0], ah[mt][1], ah[mt][2], ah[mt][3], ad);
            }
            uint32_t bh[2][4], bl[2][4];
#pragma unroll
            for (int g2 = 0; g2 < 2; g2++) {
                int row = wn * 32 + g2 * 16 + laneB_row;
                int ch  = c0 + laneB_c;
                uint32_t bd = sb + S2_BH + tile_off(row, ch);
                LDSM_X4(bh[g2][0], bh[g2][1], bh[g2][2], bh[g2][3], bd);
                LDSM_X4(bl[g2][0], bl[g2][1], bl[g2][2], bl[g2][3], bd + (S2_BL - S2_BH));
            }
#pragma unroll
            for (int mt = 0; mt < 2; mt++)
#pragma unroll
                for (int nt = 0; nt < 4; nt++) {
                    int gi = nt >> 1, pi = (nt & 1) * 2;
                    MMAF16(acc[mt][nt], ah[mt], bh[gi][pi], bh[gi][pi + 1]);
                }
#pragma unroll
            for (int mt = 0; mt < 2; mt++)
#pragma unroll
                for (int nt = 0; nt < 4; nt++) {
                    int gi = nt >> 1, pi = (nt & 1) * 2;
                    MMAF16(acc[mt][nt], ah[mt], bl[gi][pi], bl[gi][pi + 1]);
                }
        }
    }

    // epilogue: weighted scatter-add (exactly 2 adds/element)
#pragma unroll
    for (int mt = 0; mt < 2; mt++) {
#pragma unroll
        for (int half = 0; half < 2; half++) {
            int lrow = wm * 32 + mt * 16 + (lane >> 2) + half * 8;
            int rr = m0 + lrow;
            if (rr < cnt) {
                int tok = s_tok[lrow];
                float w = s_w[lrow];
                float* orow = out + (size_t)tok * DIM + n0 + wn * 32 + (lane & 3) * 2;
#pragma unroll
                for (int nt = 0; nt < 4; nt++) {
                    atomicAdd(orow + nt * 8 + 0, w * acc[mt][nt][half * 2 + 0]);
                    atomicAdd(orow + nt * 8 + 1, w * acc[mt][nt][half * 2 + 1]);
                }
            }
        }
    }
}

// ===================== launcher =============================================
extern "C" void kernel_launch(void* const* d_in, const int* in_sizes, int n_in,
                              void* d_out, int out_size) {
    const float* x  = (const float*)d_in[0];
    const float* rw = (const float*)d_in[1];
    const float* gw = (const float*)d_in[2];
    const float* uw = (const float*)d_in[3];
    const float* dw = (const float*)d_in[4];
    float* out = (float*)d_out;

    cudaFuncSetAttribute(gemm1_mma, cudaFuncAttributeMaxDynamicSharedMemorySize, G1_SMEM);
    cudaFuncSetAttribute(gemm2_mma, cudaFuncAttributeMaxDynamicSharedMemorySize, G2_SMEM);

    // launch order (harness adds 2 internal launches; ncu -s 5 -c 1 captures
    // overall launch #5 = our index 3 = gemm1_mma):
    // split_all(0) router(1) finscat(2) gemm1(3) memset(4) gemm2(5)
    {
        size_t total = (size_t)N_TOK * DIM + 3 * (size_t)NE * FF * DIM;
        split_all_kernel<<<(unsigned)(total / 2048), 256>>>(x, gw, uw, dw);
    }
    router_kernel<<<N_TOK / 8, 256>>>(x, rw);
    finscat_kernel<<<1, 256>>>(out, (long long)out_size);
    gemm1_mma<<<dim3(FF / 64, 2 * N_TOK / 128, NE), 256, G1_SMEM>>>();
    cudaMemsetAsync(out, 0, (size_t)N_TOK * DIM * sizeof(float));
    gemm2_mma<<<dim3(DIM / 64, 2 * N_TOK / 128, NE), 256, G2_SMEM>>>(out);
}